// round 4
// baseline (speedup 1.0000x reference)
#include <cuda_runtime.h>
#include <cuda_bf16.h>

// SumGoalHistory: out_t = sigmoid(init + prefix_sum(goal, axis=T)), final x2.
// goal [512, 64, 1024] fp32. One thread per 2 columns (float2), software-
// pipelined U=16 float2 loads in flight (~4.2 MB chip-wide MLP).
// Sigmoid via single-MUFU tanh.approx: sig(x) = 0.5*tanh(0.5x) + 0.5.

#define T_DIM 512
#define BD    (64 * 1024)
#define NCOL2 (BD / 2)     // 32768 float2 columns
#define U     16

__device__ __forceinline__ float fast_sigmoid(float x) {
    float t;
    asm("tanh.approx.f32 %0, %1;" : "=f"(t) : "f"(0.5f * x));
    return fmaf(0.5f, t, 0.5f);
}

__global__ __launch_bounds__(128)
void SumGoalHistory_19387482374813_kernel(const float2* __restrict__ goal,
                                          const float2* __restrict__ init_state,
                                          float2* __restrict__ out) {
    const int col = blockIdx.x * blockDim.x + threadIdx.x;  // 0 .. NCOL2-1

    float2 acc = init_state[col];
    const float2* g = goal + col;
    float2*       o = out  + col;

    float2 buf[U];
    #pragma unroll
    for (int u = 0; u < U; u++)
        buf[u] = __ldcs(g + (size_t)u * NCOL2);

    for (int t0 = 0; t0 < T_DIM - U; t0 += U) {
        float2 nxt[U];
        #pragma unroll
        for (int u = 0; u < U; u++)
            nxt[u] = __ldcs(g + (size_t)(t0 + U + u) * NCOL2);

        #pragma unroll
        for (int u = 0; u < U; u++) {
            acc.x += buf[u].x;
            acc.y += buf[u].y;
            float2 s = make_float2(fast_sigmoid(acc.x), fast_sigmoid(acc.y));
            __stcs(o + (size_t)(t0 + u) * NCOL2, s);
        }

        #pragma unroll
        for (int u = 0; u < U; u++)
            buf[u] = nxt[u];
    }

    #pragma unroll
    for (int u = 0; u < U; u++) {
        acc.x += buf[u].x;
        acc.y += buf[u].y;
        float2 s = make_float2(fast_sigmoid(acc.x), fast_sigmoid(acc.y));
        __stcs(o + (size_t)(T_DIM - U + u) * NCOL2, s);
    }

    // final_state written twice after the outputs block
    __stcs(o + (size_t)T_DIM * NCOL2,       acc);
    __stcs(o + (size_t)(T_DIM + 1) * NCOL2, acc);
}

extern "C" void kernel_launch(void* const* d_in, const int* in_sizes, int n_in,
                              void* d_out, int out_size) {
    const float2* goal = (const float2*)d_in[0];
    const float2* init = (const float2*)d_in[1];
    float2* out = (float2*)d_out;

    SumGoalHistory_19387482374813_kernel<<<NCOL2 / 128, 128>>>(goal, init, out);
}

// round 5
// speedup vs baseline: 1.1286x; 1.1286x over previous
#include <cuda_runtime.h>
#include <cuda_bf16.h>

// SumGoalHistory: out_t = sigmoid(init + prefix_sum(goal, axis=T)), final x2.
// goal [512, 64, 1024] fp32. One thread per 2 columns (float2).
// Rotating register buffer NB=32, consume-then-refill at prefetch distance NB
// -> ~32 LDG.64 in flight per thread = ~8.4 MB chip-wide (2x previous round),
// attacking the latency-limited regime (achieved BW = inflight/latency).

#define T_DIM 512
#define BD    (64 * 1024)
#define NCOL2 (BD / 2)     // 32768 float2 columns
#define NB    32

__device__ __forceinline__ float fast_sigmoid(float x) {
    float t;
    asm("tanh.approx.f32 %0, %1;" : "=f"(t) : "f"(0.5f * x));
    return fmaf(0.5f, t, 0.5f);
}

__global__ __launch_bounds__(64)
void SumGoalHistory_19387482374813_kernel(const float2* __restrict__ goal,
                                          const float2* __restrict__ init_state,
                                          float2* __restrict__ out) {
    const int col = blockIdx.x * blockDim.x + threadIdx.x;  // 0 .. NCOL2-1

    float2 acc = init_state[col];
    const float2* g = goal + col;
    float2*       o = out  + col;

    float2 buf[NB];
    // Prologue: fill the whole rotating buffer (32 independent loads in flight).
    #pragma unroll
    for (int u = 0; u < NB; u++)
        buf[u] = __ldcs(g + (size_t)u * NCOL2);

    // Main loop: consume buf[u], immediately refill it from t0+NB+u.
    // Each load has NB elements of consume-work between issue and use.
    for (int t0 = 0; t0 < T_DIM - NB; t0 += NB) {
        #pragma unroll
        for (int u = 0; u < NB; u++) {
            float2 v = buf[u];
            buf[u] = __ldcs(g + (size_t)(t0 + NB + u) * NCOL2);
            acc.x += v.x;
            acc.y += v.y;
            float2 s = make_float2(fast_sigmoid(acc.x), fast_sigmoid(acc.y));
            __stcs(o + (size_t)(t0 + u) * NCOL2, s);
        }
    }

    // Epilogue: consume the last NB elements (no refill).
    #pragma unroll
    for (int u = 0; u < NB; u++) {
        acc.x += buf[u].x;
        acc.y += buf[u].y;
        float2 s = make_float2(fast_sigmoid(acc.x), fast_sigmoid(acc.y));
        __stcs(o + (size_t)(T_DIM - NB + u) * NCOL2, s);
    }

    // final_state written twice after the outputs block
    __stcs(o + (size_t)T_DIM * NCOL2,       acc);
    __stcs(o + (size_t)(T_DIM + 1) * NCOL2, acc);
}

extern "C" void kernel_launch(void* const* d_in, const int* in_sizes, int n_in,
                              void* d_out, int out_size) {
    const float2* goal = (const float2*)d_in[0];
    const float2* init = (const float2*)d_in[1];
    float2* out = (float2*)d_out;

    SumGoalHistory_19387482374813_kernel<<<NCOL2 / 64, 64>>>(goal, init, out);
}